// round 4
// baseline (speedup 1.0000x reference)
#include <cuda_runtime.h>
#include <math.h>

#define BATCH 4
#define NPTS  4096
#define KNN   16
#define NB    32          // 2*k neighbors per point
#define NPIX  (BATCH*NPTS*NB)

typedef unsigned long long u64;

// ---------------- f32x2 packed helpers (Blackwell FFMA2 path) ----------------
__device__ __forceinline__ u64 fma2(u64 a, u64 b, u64 c) {
    u64 d; asm("fma.rn.f32x2 %0,%1,%2,%3;" : "=l"(d) : "l"(a), "l"(b), "l"(c)); return d;
}
__device__ __forceinline__ u64 mul2(u64 a, u64 b) {
    u64 d; asm("mul.rn.f32x2 %0,%1,%2;" : "=l"(d) : "l"(a), "l"(b)); return d;
}
__device__ __forceinline__ u64 add2(u64 a, u64 b) {
    u64 d; asm("add.rn.f32x2 %0,%1,%2;" : "=l"(d) : "l"(a), "l"(b)); return d;
}
__device__ __forceinline__ u64 pack2(float lo, float hi) {
    u64 d; asm("mov.b64 %0,{%1,%2};" : "=l"(d) : "f"(lo), "f"(hi)); return d;
}
__device__ __forceinline__ void unpack2(u64 v, float& lo, float& hi) {
    asm("mov.b64 {%0,%1},%2;" : "=f"(lo), "=f"(hi) : "l"(v));
}

// ---------------- device scratch ----------------
__device__ float4 g_feats[NPIX];        // (resi.x, resi.y, resi.z, dist) per pixel
__device__ float  g_grp[NPIX*3];        // gathered neighbor coords per pixel

// ---------------- KNN: one thread per query, packed-pair distances ----------------
#define TILE 2048

__global__ __launch_bounds__(64) void knn_k(const float* __restrict__ p1,
                                            const float* __restrict__ p2)
{
    const int tid   = threadIdx.x;
    const int b     = blockIdx.y;
    const int phase = blockIdx.z;                 // 0: refs=p1, 1: refs=p2
    const int n     = blockIdx.x * 64 + tid;

    const float* Q = p1 + b * 3 * NPTS;
    const float* R = (phase ? p2 : p1) + b * 3 * NPTS;

    const float qx = Q[n], qy = Q[NPTS + n], qz = Q[2*NPTS + n];
    const u64 qx2 = pack2(qx, qx), qy2 = pack2(qy, qy), qz2 = pack2(qz, qz);
    const u64 M2  = pack2(-2.f, -2.f);

    // comparisons happen in the v = rr - 2*dot domain (d2 = v + qq, same order)
    const float INF = __int_as_float(0x7f800000);
    float dl[KNN];
    int   il[KNN];
    #pragma unroll
    for (int s = 0; s < KNN; s++) { dl[s] = INF; il[s] = 0; }
    float dmax = INF;
    int   ms   = 0;

    auto ins = [&](float v, int idx) {
        #pragma unroll
        for (int s = 0; s < KNN; s++)
            if (s == ms) { dl[s] = v; il[s] = idx; }
        dmax = dl[0]; ms = 0;
        #pragma unroll
        for (int s = 1; s < KNN; s++)
            if (dl[s] > dmax) { dmax = dl[s]; ms = s; }
    };

    __shared__ float4 sxy[TILE/2];   // (x0,x1,y0,y1) per ref pair
    __shared__ float4 szs[TILE/2];   // (z0,z1,s0,s1) per ref pair (s = x^2+y^2+z^2)

    for (int t0 = 0; t0 < NPTS; t0 += TILE) {
        for (int i = tid; i < TILE/2; i += 64) {
            int r0 = t0 + 2*i, r1 = r0 + 1;
            float x0 = R[r0], x1 = R[r1];
            float y0 = R[NPTS + r0], y1 = R[NPTS + r1];
            float z0 = R[2*NPTS + r0], z1 = R[2*NPTS + r1];
            sxy[i] = make_float4(x0, x1, y0, y1);
            szs[i] = make_float4(z0, z1,
                                 x0*x0 + y0*y0 + z0*z0,
                                 x1*x1 + y1*y1 + z1*z1);
        }
        __syncthreads();

        const ulonglong2* X = (const ulonglong2*)sxy;
        const ulonglong2* Z = (const ulonglong2*)szs;

        #pragma unroll 2
        for (int i = 0; i < TILE/2; i += 2) {
            ulonglong2 xy0 = X[i], zs0 = Z[i];
            ulonglong2 xy1 = X[i+1], zs1 = Z[i+1];
            u64 d0 = fma2(qx2, xy0.x, fma2(qy2, xy0.y, mul2(qz2, zs0.x)));
            u64 v0 = fma2(M2, d0, zs0.y);
            u64 d1 = fma2(qx2, xy1.x, fma2(qy2, xy1.y, mul2(qz2, zs1.x)));
            u64 v1 = fma2(M2, d1, zs1.y);
            float a, bv, c, dv;
            unpack2(v0, a, bv);
            unpack2(v1, c, dv);
            float mn = fminf(fminf(a, bv), fminf(c, dv));
            if (mn < dmax) {                      // rare after warmup
                int base = t0 + 2*i;
                if (a  < dmax) ins(a,  base + 0);
                if (bv < dmax) ins(bv, base + 1);
                if (c  < dmax) ins(c,  base + 2);
                if (dv < dmax) ins(dv, base + 3);
            }
        }
        __syncthreads();
    }

    // emit features + gathered coords (neighbor order irrelevant downstream)
    size_t base = ((size_t)(b * NPTS + n)) * NB + phase * KNN;
    #pragma unroll
    for (int s = 0; s < KNN; s++) {
        int r = il[s];
        float rx = R[r], ry = R[NPTS + r], rz = R[2*NPTS + r];
        float dx = rx - qx, dy = ry - qy, dz = rz - qz;
        float d  = sqrtf(fmaxf(dx*dx + dy*dy + dz*dz, 1e-12f));
        g_feats[base + s] = make_float4(dx, dy, dz, d);
        g_grp[(base + s)*3 + 0] = rx;
        g_grp[(base + s)*3 + 1] = ry;
        g_grp[(base + s)*3 + 2] = rz;
    }
}

// ---------------- fused fold + MLP + max + softmax + weighted sum --------------
// thread = one (point, neighbor) pixel; lane = neighbor; warp = point
// smem layout (floats):
//   [0,4096)      W1 folded        [4096,12288)  W2 folded
//   [12288,12544) W0 folded        [12544,12608) b0
//   [12608,12672) b1               [12672,12800) b2
//   [12800,12864) S0               [12864,12928) S1
//   [12928,13056) S2
#define SMEMF 13056

__global__ __launch_bounds__(128) void mlp_k(float* __restrict__ out,
    const float* __restrict__ w0, const float* __restrict__ b0,
    const float* __restrict__ g0, const float* __restrict__ be0,
    const float* __restrict__ m0, const float* __restrict__ v0,
    const float* __restrict__ w1, const float* __restrict__ b1,
    const float* __restrict__ g1, const float* __restrict__ be1,
    const float* __restrict__ m1, const float* __restrict__ v1,
    const float* __restrict__ w2, const float* __restrict__ b2,
    const float* __restrict__ g2, const float* __restrict__ be2,
    const float* __restrict__ m2, const float* __restrict__ v2)
{
    extern __shared__ float sm[];
    float* sW1 = sm;
    float* sW2 = sm + 4096;
    float* sW0 = sm + 12288;
    float* sb0 = sm + 12544;
    float* sb1 = sm + 12608;
    float* sb2 = sm + 12672;
    float* sS0 = sm + 12800;
    float* sS1 = sm + 12864;
    float* sS2 = sm + 12928;

    const int tid = threadIdx.x;

    // fold BN (eval) into per-channel scale + bias
    if (tid < 64) {
        float s = g0[tid] * rsqrtf(v0[tid] + 1e-3f);
        sS0[tid] = s; sb0[tid] = (b0[tid] - m0[tid]) * s + be0[tid];
        float t = g1[tid] * rsqrtf(v1[tid] + 1e-3f);
        sS1[tid] = t; sb1[tid] = (b1[tid] - m1[tid]) * t + be1[tid];
    }
    if (tid < 128) {
        float s = g2[tid] * rsqrtf(v2[tid] + 1e-3f);
        sS2[tid] = s; sb2[tid] = (b2[tid] - m2[tid]) * s + be2[tid];
    }
    __syncthreads();
    for (int i = tid; i < 4096; i += 128) sW1[i] = w1[i] * sS1[i >> 6];
    for (int i = tid; i < 8192; i += 128) sW2[i] = w2[i] * sS2[i >> 6];
    for (int i = tid; i < 256;  i += 128) sW0[i] = w0[i] * sS0[i >> 2];
    __syncthreads();

    const int pt   = blockIdx.x * 4 + (tid >> 5);
    const int lane = tid & 31;

    float4 x = g_feats[(size_t)pt * NB + lane];

    // layer 0: 4 -> 64 (scalar, then pack j-pairs)
    float h0[64];
    #pragma unroll 4
    for (int c = 0; c < 64; c++) {
        float4 w = ((const float4*)sW0)[c];
        float a = fmaf(w.x, x.x, fmaf(w.y, x.y, fmaf(w.z, x.z, fmaf(w.w, x.w, sb0[c]))));
        h0[c] = fmaxf(a, 0.f);
    }
    u64 h0p[32];
    #pragma unroll
    for (int p = 0; p < 32; p++) h0p[p] = pack2(h0[2*p], h0[2*p+1]);

    // layer 1: 64 -> 64, packed over the reduction axis
    float h1[64];
    #pragma unroll 4
    for (int c = 0; c < 64; c++) {
        const ulonglong2* wr = (const ulonglong2*)(sW1 + c * 64);
        u64 a0 = 0ull, a1 = 0ull;
        #pragma unroll
        for (int j = 0; j < 16; j++) {
            ulonglong2 w = wr[j];
            a0 = fma2(w.x, h0p[2*j],     a0);
            a1 = fma2(w.y, h0p[2*j + 1], a1);
        }
        float lo, hi; unpack2(add2(a0, a1), lo, hi);
        h1[c] = fmaxf(sb1[c] + lo + hi, 0.f);
    }
    u64 h1p[32];
    #pragma unroll
    for (int p = 0; p < 32; p++) h1p[p] = pack2(h1[2*p], h1[2*p+1]);

    // layer 2: 64 -> 128, keep only running channel max
    float mx = -__int_as_float(0x7f800000);
    #pragma unroll 4
    for (int c = 0; c < 128; c++) {
        const ulonglong2* wr = (const ulonglong2*)(sW2 + c * 64);
        u64 a0 = 0ull, a1 = 0ull;
        #pragma unroll
        for (int j = 0; j < 16; j++) {
            ulonglong2 w = wr[j];
            a0 = fma2(w.x, h1p[2*j],     a0);
            a1 = fma2(w.y, h1p[2*j + 1], a1);
        }
        float lo, hi; unpack2(add2(a0, a1), lo, hi);
        float v = fmaxf(sb2[c] + lo + hi, 0.f);
        mx = fmaxf(mx, v);
    }

    // softmax over the 32 neighbors (lanes) + weighted sum of gathered coords
    float M = mx;
    #pragma unroll
    for (int o = 16; o; o >>= 1) M = fmaxf(M, __shfl_xor_sync(0xffffffffu, M, o));
    float e = expf(mx - M);
    float S = e;
    #pragma unroll
    for (int o = 16; o; o >>= 1) S += __shfl_xor_sync(0xffffffffu, S, o);
    float w = e / S;

    size_t gb = ((size_t)pt * NB + lane) * 3;
    float sx = w * g_grp[gb + 0];
    float sy = w * g_grp[gb + 1];
    float sz = w * g_grp[gb + 2];
    #pragma unroll
    for (int o = 16; o; o >>= 1) {
        sx += __shfl_xor_sync(0xffffffffu, sx, o);
        sy += __shfl_xor_sync(0xffffffffu, sy, o);
        sz += __shfl_xor_sync(0xffffffffu, sz, o);
    }
    if (lane == 0) {
        int b = pt >> 12;
        int n = pt & (NPTS - 1);
        out[(b*3 + 0) * NPTS + n] = sx;
        out[(b*3 + 1) * NPTS + n] = sy;
        out[(b*3 + 2) * NPTS + n] = sz;
    }
}

// ---------------- launch ----------------
extern "C" void kernel_launch(void* const* d_in, const int* in_sizes, int n_in,
                              void* d_out, int out_size)
{
    const float* p1 = (const float*)d_in[0];
    const float* p2 = (const float*)d_in[1];
    // d_in[2] = k (fixed at 16)
    const float* w0  = (const float*)d_in[3];
    const float* b0  = (const float*)d_in[4];
    const float* g0  = (const float*)d_in[5];
    const float* be0 = (const float*)d_in[6];
    const float* m0  = (const float*)d_in[7];
    const float* v0  = (const float*)d_in[8];
    const float* w1  = (const float*)d_in[9];
    const float* b1  = (const float*)d_in[10];
    const float* g1  = (const float*)d_in[11];
    const float* be1 = (const float*)d_in[12];
    const float* m1  = (const float*)d_in[13];
    const float* v1  = (const float*)d_in[14];
    const float* w2  = (const float*)d_in[15];
    const float* b2  = (const float*)d_in[16];
    const float* g2  = (const float*)d_in[17];
    const float* be2 = (const float*)d_in[18];
    const float* m2  = (const float*)d_in[19];
    const float* v2  = (const float*)d_in[20];

    cudaFuncSetAttribute(mlp_k, cudaFuncAttributeMaxDynamicSharedMemorySize,
                         SMEMF * (int)sizeof(float));

    knn_k<<<dim3(NPTS/64, BATCH, 2), 64>>>(p1, p2);

    mlp_k<<<BATCH*NPTS/4, 128, SMEMF * (int)sizeof(float)>>>((float*)d_out,
        w0, b0, g0, be0, m0, v0,
        w1, b1, g1, be1, m1, v1,
        w2, b2, g2, be2, m2, v2);
}

// round 7
// speedup vs baseline: 1.7335x; 1.7335x over previous
#include <cuda_runtime.h>
#include <math.h>

#define BATCH 4
#define NPTS  4096
#define KNN   16
#define NB    32          // 2*k neighbors per point
#define NPIX  (BATCH*NPTS*NB)

typedef unsigned long long u64;

// ---------------- f32x2 packed helpers (Blackwell FFMA2 path) ----------------
__device__ __forceinline__ u64 fma2(u64 a, u64 b, u64 c) {
    u64 d; asm("fma.rn.f32x2 %0,%1,%2,%3;" : "=l"(d) : "l"(a), "l"(b), "l"(c)); return d;
}
__device__ __forceinline__ u64 add2(u64 a, u64 b) {
    u64 d; asm("add.rn.f32x2 %0,%1,%2;" : "=l"(d) : "l"(a), "l"(b)); return d;
}
__device__ __forceinline__ u64 pack2(float lo, float hi) {
    u64 d; asm("mov.b64 %0,{%1,%2};" : "=l"(d) : "f"(lo), "f"(hi)); return d;
}
__device__ __forceinline__ void unpack2(u64 v, float& lo, float& hi) {
    asm("mov.b64 {%0,%1},%2;" : "=f"(lo), "=f"(hi) : "l"(v));
}

// ---------------- device scratch ----------------
__device__ float4 g_feats[NPIX];        // (resi.x, resi.y, resi.z, dist) per pixel
__device__ float  g_grp[NPIX*3];        // gathered neighbor coords per pixel

// ---------------- KNN (round-1 proven version): one thread per query ----------------
#define TILE 2048

__global__ __launch_bounds__(64) void knn_k(const float* __restrict__ p1,
                                            const float* __restrict__ p2)
{
    const int tid   = threadIdx.x;
    const int b     = blockIdx.y;
    const int phase = blockIdx.z;                 // 0: refs=p1, 1: refs=p2
    const int n     = blockIdx.x * 64 + tid;

    const float* Q = p1 + b * 3 * NPTS;
    const float* R = (phase ? p2 : p1) + b * 3 * NPTS;

    const float qx = Q[n], qy = Q[NPTS + n], qz = Q[2*NPTS + n];
    const float qq = qx*qx + qy*qy + qz*qz;

    const float INF = __int_as_float(0x7f800000);
    float dl[KNN];
    int   il[KNN];
    #pragma unroll
    for (int s = 0; s < KNN; s++) { dl[s] = INF; il[s] = 0; }
    float dmax = INF;
    int   ms   = 0;

    __shared__ float4 sref[TILE];

    for (int t0 = 0; t0 < NPTS; t0 += TILE) {
        for (int i = tid; i < TILE; i += 64) {
            int r = t0 + i;
            float rx = R[r], ry = R[NPTS + r], rz = R[2*NPTS + r];
            sref[i] = make_float4(rx, ry, rz, rx*rx + ry*ry + rz*rz);
        }
        __syncthreads();

        #pragma unroll 4
        for (int i = 0; i < TILE; i++) {
            float4 rv  = sref[i];
            float dot  = fmaf(qx, rv.x, fmaf(qy, rv.y, qz * rv.z));
            float d2   = fmaf(-2.f, dot, qq + rv.w);
            if (d2 < dmax) {
                // replace current max slot, then rescan for new max (branchless slots)
                #pragma unroll
                for (int s = 0; s < KNN; s++)
                    if (s == ms) { dl[s] = d2; il[s] = t0 + i; }
                dmax = dl[0]; ms = 0;
                #pragma unroll
                for (int s = 1; s < KNN; s++)
                    if (dl[s] > dmax) { dmax = dl[s]; ms = s; }
            }
        }
        __syncthreads();
    }

    // emit features + gathered coords (neighbor order irrelevant downstream)
    size_t base = ((size_t)(b * NPTS + n)) * NB + phase * KNN;
    #pragma unroll
    for (int s = 0; s < KNN; s++) {
        int r = il[s];
        float rx = R[r], ry = R[NPTS + r], rz = R[2*NPTS + r];
        float dx = rx - qx, dy = ry - qy, dz = rz - qz;
        float d  = sqrtf(fmaxf(dx*dx + dy*dy + dz*dz, 1e-12f));
        g_feats[base + s] = make_float4(dx, dy, dz, d);
        g_grp[(base + s)*3 + 0] = rx;
        g_grp[(base + s)*3 + 1] = ry;
        g_grp[(base + s)*3 + 2] = rz;
    }
}

// ---------------- fused fold + MLP + max + softmax + weighted sum --------------
// 2 pixels per thread: warp = 2 points; lanes 0-15 -> point A, lanes 16-31 -> point B.
// Lane handles neighbors (lane&15) and (lane&15)+16 of its point. Layer 2 is joint
// (one weight LDS feeds both pixels); softmax reduces over the 16-lane half-warp.
// smem layout (floats):
//   [0,4096)      W1 folded        [4096,12288)  W2 folded
//   [12288,12544) W0 folded        [12544,12608) b0
//   [12608,12672) b1               [12672,12800) b2
//   [12800,12864) S0               [12864,12928) S1
//   [12928,13056) S2
#define SMEMF 13056

// layers 0+1 for one pixel -> packed h1 (32 x f32x2)
__device__ __forceinline__ void layer01(float4 x,
                                        const float* __restrict__ sW0,
                                        const float* __restrict__ sb0,
                                        const float* __restrict__ sW1,
                                        const float* __restrict__ sb1,
                                        u64 h1p[32])
{
    u64 h0p[32];
    #pragma unroll 4
    for (int c = 0; c < 64; c += 2) {
        float4 wa = ((const float4*)sW0)[c];
        float4 wb = ((const float4*)sW0)[c + 1];
        float a = fmaf(wa.x, x.x, fmaf(wa.y, x.y, fmaf(wa.z, x.z, fmaf(wa.w, x.w, sb0[c]))));
        float b = fmaf(wb.x, x.x, fmaf(wb.y, x.y, fmaf(wb.z, x.z, fmaf(wb.w, x.w, sb0[c+1]))));
        h0p[c >> 1] = pack2(fmaxf(a, 0.f), fmaxf(b, 0.f));
    }
    #pragma unroll 2
    for (int c = 0; c < 64; c += 2) {
        const ulonglong2* wr0 = (const ulonglong2*)(sW1 + c * 64);
        const ulonglong2* wr1 = (const ulonglong2*)(sW1 + (c + 1) * 64);
        u64 a0 = 0ull, a1 = 0ull, b0 = 0ull, b1 = 0ull;
        #pragma unroll
        for (int j = 0; j < 16; j++) {
            ulonglong2 w0 = wr0[j];
            ulonglong2 w1 = wr1[j];
            a0 = fma2(w0.x, h0p[2*j],     a0);
            a1 = fma2(w0.y, h0p[2*j + 1], a1);
            b0 = fma2(w1.x, h0p[2*j],     b0);
            b1 = fma2(w1.y, h0p[2*j + 1], b1);
        }
        float alo, ahi, blo, bhi;
        unpack2(add2(a0, a1), alo, ahi);
        unpack2(add2(b0, b1), blo, bhi);
        h1p[c >> 1] = pack2(fmaxf(sb1[c]   + alo + ahi, 0.f),
                            fmaxf(sb1[c+1] + blo + bhi, 0.f));
    }
}

__global__ __launch_bounds__(128) void mlp_k(float* __restrict__ out,
    const float* __restrict__ w0, const float* __restrict__ b0,
    const float* __restrict__ g0, const float* __restrict__ be0,
    const float* __restrict__ m0, const float* __restrict__ v0,
    const float* __restrict__ w1, const float* __restrict__ b1,
    const float* __restrict__ g1, const float* __restrict__ be1,
    const float* __restrict__ m1, const float* __restrict__ v1,
    const float* __restrict__ w2, const float* __restrict__ b2,
    const float* __restrict__ g2, const float* __restrict__ be2,
    const float* __restrict__ m2, const float* __restrict__ v2)
{
    extern __shared__ float sm[];
    float* sW1 = sm;
    float* sW2 = sm + 4096;
    float* sW0 = sm + 12288;
    float* sb0 = sm + 12544;
    float* sb1 = sm + 12608;
    float* sb2 = sm + 12672;
    float* sS0 = sm + 12800;
    float* sS1 = sm + 12864;
    float* sS2 = sm + 12928;

    const int tid = threadIdx.x;

    // fold BN (eval) into per-channel scale + bias
    if (tid < 64) {
        float s = g0[tid] * rsqrtf(v0[tid] + 1e-3f);
        sS0[tid] = s; sb0[tid] = (b0[tid] - m0[tid]) * s + be0[tid];
        float t = g1[tid] * rsqrtf(v1[tid] + 1e-3f);
        sS1[tid] = t; sb1[tid] = (b1[tid] - m1[tid]) * t + be1[tid];
    }
    if (tid < 128) {
        float s = g2[tid] * rsqrtf(v2[tid] + 1e-3f);
        sS2[tid] = s; sb2[tid] = (b2[tid] - m2[tid]) * s + be2[tid];
    }
    __syncthreads();
    for (int i = tid; i < 4096; i += 128) sW1[i] = w1[i] * sS1[i >> 6];
    for (int i = tid; i < 8192; i += 128) sW2[i] = w2[i] * sS2[i >> 6];
    for (int i = tid; i < 256;  i += 128) sW0[i] = w0[i] * sS0[i >> 2];
    __syncthreads();

    const int warp = tid >> 5;
    const int lane = tid & 31;
    const int pt   = blockIdx.x * 8 + warp * 2 + (lane >> 4);  // 8 points per block
    const int nb   = lane & 15;

    const size_t pixA = (size_t)pt * NB + nb;        // neighbor nb
    const size_t pixB = pixA + 16;                   // neighbor nb+16

    // layers 0-1, sequential per pixel (keeps register peak ~3x64)
    u64 h1pA[32], h1pB[32];
    layer01(g_feats[pixA], sW0, sb0, sW1, sb1, h1pA);
    layer01(g_feats[pixB], sW0, sb0, sW1, sb1, h1pB);

    // layer 2: 64 -> 128 joint over both pixels; one weight load feeds 4 fma2
    float mxA = -__int_as_float(0x7f800000);
    float mxB = mxA;
    #pragma unroll 2
    for (int c = 0; c < 128; c++) {
        const ulonglong2* wr = (const ulonglong2*)(sW2 + c * 64);
        u64 a0 = 0ull, a1 = 0ull, c0 = 0ull, c1 = 0ull;
        #pragma unroll
        for (int j = 0; j < 16; j++) {
            ulonglong2 w = wr[j];
            a0 = fma2(w.x, h1pA[2*j],     a0);
            a1 = fma2(w.y, h1pA[2*j + 1], a1);
            c0 = fma2(w.x, h1pB[2*j],     c0);
            c1 = fma2(w.y, h1pB[2*j + 1], c1);
        }
        float alo, ahi, blo, bhi;
        unpack2(add2(a0, a1), alo, ahi);
        unpack2(add2(c0, c1), blo, bhi);
        float bias = sb2[c];
        mxA = fmaxf(mxA, fmaxf(bias + alo + ahi, 0.f));
        mxB = fmaxf(mxB, fmaxf(bias + blo + bhi, 0.f));
    }

    // softmax over the 32 neighbors of this point (16 lanes x 2 pixels each)
    float M = fmaxf(mxA, mxB);
    #pragma unroll
    for (int o = 8; o; o >>= 1) M = fmaxf(M, __shfl_xor_sync(0xffffffffu, M, o));
    float eA = expf(mxA - M);
    float eB = expf(mxB - M);
    float S = eA + eB;
    #pragma unroll
    for (int o = 8; o; o >>= 1) S += __shfl_xor_sync(0xffffffffu, S, o);
    float wA = eA / S;
    float wB = eB / S;

    size_t ga = pixA * 3, gb = pixB * 3;
    float sx = fmaf(wA, g_grp[ga + 0], wB * g_grp[gb + 0]);
    float sy = fmaf(wA, g_grp[ga + 1], wB * g_grp[gb + 1]);
    float sz = fmaf(wA, g_grp[ga + 2], wB * g_grp[gb + 2]);
    #pragma unroll
    for (int o = 8; o; o >>= 1) {
        sx += __shfl_xor_sync(0xffffffffu, sx, o);
        sy += __shfl_xor_sync(0xffffffffu, sy, o);
        sz += __shfl_xor_sync(0xffffffffu, sz, o);
    }
    if (nb == 0) {
        int b = pt >> 12;
        int n = pt & (NPTS - 1);
        out[(b*3 + 0) * NPTS + n] = sx;
        out[(b*3 + 1) * NPTS + n] = sy;
        out[(b*3 + 2) * NPTS + n] = sz;
    }
}

// ---------------- launch ----------------
extern "C" void kernel_launch(void* const* d_in, const int* in_sizes, int n_in,
                              void* d_out, int out_size)
{
    const float* p1 = (const float*)d_in[0];
    const float* p2 = (const float*)d_in[1];
    // d_in[2] = k (fixed at 16)
    const float* w0  = (const float*)d_in[3];
    const float* b0  = (const float*)d_in[4];
    const float* g0  = (const float*)d_in[5];
    const float* be0 = (const float*)d_in[6];
    const float* m0  = (const float*)d_in[7];
    const float* v0  = (const float*)d_in[8];
    const float* w1  = (const float*)d_in[9];
    const float* b1  = (const float*)d_in[10];
    const float* g1  = (const float*)d_in[11];
    const float* be1 = (const float*)d_in[12];
    const float* m1  = (const float*)d_in[13];
    const float* v1  = (const float*)d_in[14];
    const float* w2  = (const float*)d_in[15];
    const float* b2  = (const float*)d_in[16];
    const float* g2  = (const float*)d_in[17];
    const float* be2 = (const float*)d_in[18];
    const float* m2  = (const float*)d_in[19];
    const float* v2  = (const float*)d_in[20];

    cudaFuncSetAttribute(mlp_k, cudaFuncAttributeMaxDynamicSharedMemorySize,
                         SMEMF * (int)sizeof(float));

    knn_k<<<dim3(NPTS/64, BATCH, 2), 64>>>(p1, p2);

    mlp_k<<<BATCH*NPTS/8, 128, SMEMF * (int)sizeof(float)>>>((float*)d_out,
        w0, b0, g0, be0, m0, v0,
        w1, b1, g1, be1, m1, v1,
        w2, b2, g2, be2, m2, v2);
}